// round 8
// baseline (speedup 1.0000x reference)
#include <cuda_runtime.h>

typedef unsigned long long u64;

// ---- packed f32x2 helpers (SASS FADD2/FMUL2/FFMA2 — PTX-only) ----
__device__ __forceinline__ u64 pk2(float lo, float hi) {
    u64 r; asm("mov.b64 %0, {%1, %2};" : "=l"(r) : "f"(lo), "f"(hi)); return r;
}
__device__ __forceinline__ void upk2(u64 v, float& a, float& b) {
    asm("mov.b64 {%0, %1}, %2;" : "=f"(a), "=f"(b) : "l"(v));
}
__device__ __forceinline__ u64 add2(u64 a, u64 b) {
    u64 r; asm("add.rn.f32x2 %0, %1, %2;" : "=l"(r) : "l"(a), "l"(b)); return r;
}
__device__ __forceinline__ u64 mul2(u64 a, u64 b) {
    u64 r; asm("mul.rn.f32x2 %0, %1, %2;" : "=l"(r) : "l"(a), "l"(b)); return r;
}
__device__ __forceinline__ u64 fma2_(u64 a, u64 b, u64 c) {
    u64 r; asm("fma.rn.f32x2 %0, %1, %2, %3;" : "=l"(r) : "l"(a), "l"(b), "l"(c)); return r;
}
__device__ __forceinline__ u64 abs2(u64 a) { return a & 0x7FFFFFFF7FFFFFFFULL; }
__device__ __forceinline__ u64 neg2(u64 a) { return a ^ 0x8000000080000000ULL; }

// Per-box preprocessed params: cx, cy, cos, sin, hx, hy, pad, pad  (8 floats)
#define MAXB 8192
__device__ float g_params[MAXB * 8];

__global__ void prep_kernel(const float* __restrict__ boxes, int nb) {
    int i = blockIdx.x * blockDim.x + threadIdx.x;
    if (i >= nb) return;
    float cx = boxes[i * 5 + 0];
    float cy = boxes[i * 5 + 1];
    float hx = boxes[i * 5 + 2] * 0.5f;
    float hy = boxes[i * 5 + 3] * 0.5f;
    float ang = boxes[i * 5 + 4];
    float s, c;
    sincosf(ang, &s, &c);
    float4* p = reinterpret_cast<float4*>(&g_params[i * 8]);
    p[0] = make_float4(cx, cy, c, s);
    p[1] = make_float4(hx, hy, 0.0f, 0.0f);
}

// Scalar tail of closed-form 1-D GIoU:
//   o = a - |q|;  m = min(min(tr1, tr2), o);  g = m / (2a - m)
__device__ __forceinline__ float giou_tail(float a, float tr1, float tr2, float q) {
    float o = a - fabsf(q);              // FADD with |src| modifier
    float m = fminf(fminf(tr1, tr2), o);
    float den = fmaf(a, 2.0f, -m);
    return __fdividef(m, den);
}

#define TILE 64

__global__ __launch_bounds__(256) void pair_kernel(float* __restrict__ out, int nb) {
    __shared__ __align__(16) float s_cx[128];
    __shared__ __align__(16) float s_cy[128];
    __shared__ __align__(16) float s_c [128];
    __shared__ __align__(16) float s_s [128];
    __shared__ __align__(16) float s_hx[128];
    __shared__ __align__(16) float s_hy[128];

    const int i0 = blockIdx.y * TILE;
    const int j0 = blockIdx.x * TILE;
    const int tid = threadIdx.x;

    {
        int which = tid >> 7;
        int slot  = (tid >> 1) & 63;
        int half  = tid & 1;
        int gidx  = (which ? j0 : i0) + slot;
        float4 v = half ? make_float4(1.0f, 1.0f, 0.0f, 0.0f)
                        : make_float4(0.0f, 0.0f, 1.0f, 0.0f);
        if (gidx < nb)
            v = reinterpret_cast<const float4*>(g_params)[gidx * 2 + half];
        int d = which * 64 + slot;
        if (half == 0) {
            s_cx[d] = v.x; s_cy[d] = v.y; s_c[d] = v.z; s_s[d] = v.w;
        } else {
            s_hx[d] = v.x; s_hy[d] = v.y;
        }
    }
    __syncthreads();

    const int tx = tid & 15;
    const int ty = tid >> 4;
    const int ib = ty * 4;
    const int jb = tx * 4;

    // j-tile params: LDS.128 then pack into f32x2 lanes (2 jj per lane-pair)
    float4 CXJ = *reinterpret_cast<const float4*>(&s_cx[64 + jb]);
    float4 CYJ = *reinterpret_cast<const float4*>(&s_cy[64 + jb]);
    float4 CJ4 = *reinterpret_cast<const float4*>(&s_c [64 + jb]);
    float4 SJ4 = *reinterpret_cast<const float4*>(&s_s [64 + jb]);
    float4 HXJ = *reinterpret_cast<const float4*>(&s_hx[64 + jb]);
    float4 HYJ = *reinterpret_cast<const float4*>(&s_hy[64 + jb]);

    u64 cxj[2], cyj[2], cj[2], sj[2], sjn[2], hxj[2], hyj[2];
    cxj[0] = pk2(CXJ.x, CXJ.y); cxj[1] = pk2(CXJ.z, CXJ.w);
    cyj[0] = pk2(CYJ.x, CYJ.y); cyj[1] = pk2(CYJ.z, CYJ.w);
    cj [0] = pk2(CJ4.x, CJ4.y); cj [1] = pk2(CJ4.z, CJ4.w);
    sj [0] = pk2(SJ4.x, SJ4.y); sj [1] = pk2(SJ4.z, SJ4.w);
    hxj[0] = pk2(HXJ.x, HXJ.y); hxj[1] = pk2(HXJ.z, HXJ.w);
    hyj[0] = pk2(HYJ.x, HYJ.y); hyj[1] = pk2(HYJ.z, HYJ.w);
    sjn[0] = neg2(sj[0]);       sjn[1] = neg2(sj[1]);
    // doubled j half-extents (tr1 for axes 3/4), scalar per jj
    float thxj2[4] = {HXJ.x + HXJ.x, HXJ.y + HXJ.y, HXJ.z + HXJ.z, HXJ.w + HXJ.w};
    float thyj2[4] = {HYJ.x + HYJ.x, HYJ.y + HYJ.y, HYJ.z + HYJ.z, HYJ.w + HYJ.w};

    const bool diagblk = (i0 == j0);

#pragma unroll
    for (int ii = 0; ii < 4; ii++) {
        const float cxi = s_cx[ib + ii];
        const float cyi = s_cy[ib + ii];
        const float ci  = s_c [ib + ii];
        const float si  = s_s [ib + ii];
        const float hxi = s_hx[ib + ii];
        const float hyi = s_hy[ib + ii];
        const int gi = i0 + ib + ii;

        // broadcast packs for this i-box
        const u64 pci  = pk2(ci, ci);
        const u64 psi  = pk2(si, si);
        const u64 pnci = neg2(pci);
        const u64 pnsi = neg2(psi);
        const u64 pncx = pk2(-cxi, -cxi);
        const u64 pncy = pk2(-cyi, -cyi);
        const u64 phxi = pk2(hxi, hxi);
        const u64 phyi = pk2(hyi, hyi);
        const float thxi2 = hxi + hxi;
        const float thyi2 = hyi + hyi;

        float4 res;
        float* resf = &res.x;

#pragma unroll
        for (int p = 0; p < 2; p++) {
            // packed over 2 j-boxes; signs of cd/sd/q* are irrelevant (abs later)
            u64 dx = add2(cxj[p], pncx);
            u64 dy = add2(cyj[p], pncy);
            u64 cd = fma2_(pci, cj[p], mul2(psi, sj[p]));
            u64 sd = fma2_(psi, cj[p], mul2(pnci, sj[p]));
            u64 A  = abs2(cd);
            u64 B  = abs2(sd);
            u64 q1 = fma2_(dx, pci,   mul2(dy, pnsi));
            u64 q2 = fma2_(dx, psi,   mul2(dy, pci));
            u64 q3 = fma2_(dx, cj[p], mul2(dy, sjn[p]));
            u64 q4 = fma2_(dx, sj[p], mul2(dy, cj[p]));
            u64 r21 = fma2_(hxj[p], A, mul2(hyj[p], B));
            u64 r22 = fma2_(hxj[p], B, mul2(hyj[p], A));
            u64 r23 = fma2_(phxi,  A, mul2(phyi,  B));
            u64 r24 = fma2_(phxi,  B, mul2(phyi,  A));
            u64 a1 = add2(phxi,   r21);
            u64 a2 = add2(phyi,   r22);
            u64 a3 = add2(hxj[p], r23);
            u64 a4 = add2(hyj[p], r24);
            u64 d1 = add2(r21, r21);   // 2*r2 per axis (tr2)
            u64 d2 = add2(r22, r22);
            u64 d3 = add2(r23, r23);
            u64 d4 = add2(r24, r24);

            float a1a, a1b, a2a, a2b, a3a, a3b, a4a, a4b;
            float d1a, d1b, d2a, d2b, d3a, d3b, d4a, d4b;
            float q1a, q1b, q2a, q2b, q3a, q3b, q4a, q4b;
            upk2(a1, a1a, a1b); upk2(a2, a2a, a2b); upk2(a3, a3a, a3b); upk2(a4, a4a, a4b);
            upk2(d1, d1a, d1b); upk2(d2, d2a, d2b); upk2(d3, d3a, d3b); upk2(d4, d4a, d4b);
            upk2(q1, q1a, q1b); upk2(q2, q2a, q2b); upk2(q3, q3a, q3b); upk2(q4, q4a, q4b);

            // lane 0 (jj = 2p)
            {
                float g1 = giou_tail(a1a, thxi2,        d1a, q1a);
                float g2 = giou_tail(a2a, thyi2,        d2a, q2a);
                float g3 = giou_tail(a3a, thxj2[2*p],   d3a, q3a);
                float g4 = giou_tail(a4a, thyj2[2*p],   d4a, q4a);
                float g = fminf(fminf(g1, g2), fminf(g3, g4));
                resf[2*p] = fmaxf(g, 0.0f);
            }
            // lane 1 (jj = 2p+1)
            {
                float g1 = giou_tail(a1b, thxi2,        d1b, q1b);
                float g2 = giou_tail(a2b, thyi2,        d2b, q2b);
                float g3 = giou_tail(a3b, thxj2[2*p+1], d3b, q3b);
                float g4 = giou_tail(a4b, thyj2[2*p+1], d4b, q4b);
                float g = fminf(fminf(g1, g2), fminf(g3, g4));
                resf[2*p+1] = fmaxf(g, 0.0f);
            }
        }

        if (diagblk) {
            int dj = (ib + ii) - jb;
            if (dj >= 0 && dj < 4) resf[dj] = 0.0f;
        }

        const int gjbase = j0 + jb;
        if (gi < nb && gjbase + 3 < nb) {
            *reinterpret_cast<float4*>(&out[(size_t)gi * nb + gjbase]) = res;
        } else if (gi < nb) {
#pragma unroll
            for (int jj = 0; jj < 4; jj++)
                if (gjbase + jj < nb) out[(size_t)gi * nb + gjbase + jj] = resf[jj];
        }
    }
}

extern "C" void kernel_launch(void* const* d_in, const int* in_sizes, int n_in,
                              void* d_out, int out_size) {
    const float* boxes = (const float*)d_in[0];
    float* out = (float*)d_out;
    const int nb = in_sizes[0] / 5;

    prep_kernel<<<(nb + 255) / 256, 256>>>(boxes, nb);

    dim3 grid((nb + TILE - 1) / TILE, (nb + TILE - 1) / TILE);
    pair_kernel<<<grid, 256>>>(out, nb);
}

// round 9
// speedup vs baseline: 1.4775x; 1.4775x over previous
#include <cuda_runtime.h>

// Per-box preprocessed params: cx, cy, cos, sin, hx, hy, pad, pad  (8 floats)
#define MAXB 8192
__device__ float g_params[MAXB * 8];

__global__ void prep_kernel(const float* __restrict__ boxes, int nb) {
    int i = blockIdx.x * blockDim.x + threadIdx.x;
    if (i >= nb) return;
    float cx = boxes[i * 5 + 0];
    float cy = boxes[i * 5 + 1];
    float hx = boxes[i * 5 + 2] * 0.5f;
    float hy = boxes[i * 5 + 3] * 0.5f;
    float ang = boxes[i * 5 + 4];
    float s, c;
    sincosf(ang, &s, &c);
    float4* p = reinterpret_cast<float4*>(&g_params[i * 8]);
    p[0] = make_float4(cx, cy, c, s);
    p[1] = make_float4(hx, hy, 0.0f, 0.0f);
}

// 1-D GIoU of [-r1, r1] vs [d-r2, d+r2], d = |q| — fully closed form:
//   a = r1+r2;  t = max(|r1-r2|, |q|);  g = (a-t)/(a+t)
__device__ __forceinline__ float giou_axis(float r1, float r2, float q) {
    float a = r1 + r2;
    float t = fmaxf(fabsf(r1 - r2), fabsf(q));
    return __fdividef(a - t, a + t);
}

#define TILE 64

__global__ __launch_bounds__(256) void pair_kernel(float* __restrict__ out, int nb, int T) {
    // Map linear block index -> upper-triangular tile pair (r <= c)
    const int b = blockIdx.x;
    float Tf = (float)T;
    int r = (int)floorf(((2.0f * Tf + 1.0f) -
                sqrtf((2.0f * Tf + 1.0f) * (2.0f * Tf + 1.0f) - 8.0f * (float)b)) * 0.5f);
    if (r < 0) r = 0;
    if (r > T - 1) r = T - 1;
    while (r > 0 && r * T - (r * (r - 1)) / 2 > b) --r;
    while ((r + 1) * T - ((r + 1) * r) / 2 <= b) ++r;
    const int c = r + (b - (r * T - (r * (r - 1)) / 2));

    const int i0 = r * TILE;
    const int j0 = c * TILE;
    const int tid = threadIdx.x;

    // SoA shared layout: [0,64) = i-tile, [64,128) = j-tile (16B aligned)
    __shared__ __align__(16) float s_cx[128];
    __shared__ __align__(16) float s_cy[128];
    __shared__ __align__(16) float s_c [128];
    __shared__ __align__(16) float s_s [128];
    __shared__ __align__(16) float s_hx[128];
    __shared__ __align__(16) float s_hy[128];

    {
        int which = tid >> 7;          // 0 -> i tile, 1 -> j tile
        int slot  = (tid >> 1) & 63;
        int half  = tid & 1;
        int gidx  = (which ? j0 : i0) + slot;
        float4 v = half ? make_float4(1.0f, 1.0f, 0.0f, 0.0f)
                        : make_float4(0.0f, 0.0f, 1.0f, 0.0f);
        if (gidx < nb)
            v = reinterpret_cast<const float4*>(g_params)[gidx * 2 + half];
        int d = which * 64 + slot;
        if (half == 0) {
            s_cx[d] = v.x; s_cy[d] = v.y; s_c[d] = v.z; s_s[d] = v.w;
        } else {
            s_hx[d] = v.x; s_hy[d] = v.y;
        }
    }
    __syncthreads();

    const int tx = tid & 15;   // j sub-tile (4 boxes)
    const int ty = tid >> 4;   // i sub-tile (4 boxes)
    const int ib = ty * 4;
    const int jb = tx * 4;

    // Hoist the 4 j-box params via LDS.128 from SoA
    float4 CXJ = *reinterpret_cast<const float4*>(&s_cx[64 + jb]);
    float4 CYJ = *reinterpret_cast<const float4*>(&s_cy[64 + jb]);
    float4 CJ4 = *reinterpret_cast<const float4*>(&s_c [64 + jb]);
    float4 SJ4 = *reinterpret_cast<const float4*>(&s_s [64 + jb]);
    float4 HXJ = *reinterpret_cast<const float4*>(&s_hx[64 + jb]);
    float4 HYJ = *reinterpret_cast<const float4*>(&s_hy[64 + jb]);
    const float* cxj = &CXJ.x;
    const float* cyj = &CYJ.x;
    const float* cj  = &CJ4.x;
    const float* sj  = &SJ4.x;
    const float* hxj = &HXJ.x;
    const float* hyj = &HYJ.x;

    const bool diagblk = (i0 == j0);

    float4 res[4];   // res[ii] = row of 4 results (constant-indexed after unroll)

#pragma unroll
    for (int ii = 0; ii < 4; ii++) {
        const float cxi = s_cx[ib + ii];
        const float cyi = s_cy[ib + ii];
        const float ci  = s_c [ib + ii];
        const float si  = s_s [ib + ii];
        const float hxi = s_hx[ib + ii];
        const float hyi = s_hy[ib + ii];

        float* resf = &res[ii].x;
#pragma unroll
        for (int jj = 0; jj < 4; jj++) {
            const float dx = cxj[jj] - cxi;
            const float dy = cyj[jj] - cyi;
            // cos/sin of angle difference (signs irrelevant: only |.| used)
            const float cd = fmaf(ci, cj[jj], si * sj[jj]);
            const float sd = fmaf(si, cj[jj], -(ci * sj[jj]));
            const float A  = fabsf(cd);
            const float Bb = fabsf(sd);
            // center-delta projections on the 4 unit axes (|.| in giou_axis)
            const float q1 = fmaf(dx, ci, -(dy * si));
            const float q2 = fmaf(dx, si, dy * ci);
            const float q3 = fmaf(dx, cj[jj], -(dy * sj[jj]));
            const float q4 = fmaf(dx, sj[jj], dy * cj[jj]);
            // other-box radii on each axis
            const float r21 = fmaf(hxj[jj], A,  hyj[jj] * Bb);
            const float r22 = fmaf(hxj[jj], Bb, hyj[jj] * A);
            const float r23 = fmaf(hxi,     A,  hyi * Bb);
            const float r24 = fmaf(hxi,     Bb, hyi * A);

            float g1 = giou_axis(hxi,     r21, q1);
            float g2 = giou_axis(hyi,     r22, q2);
            float g3 = giou_axis(hxj[jj], r23, q3);
            float g4 = giou_axis(hyj[jj], r24, q4);

            float g = fminf(fminf(g1, g2), fminf(g3, g4));
            resf[jj] = fmaxf(g, 0.0f);
        }

        // Diagonal fixup: uniform branch, only diagonal tiles pay
        if (diagblk) {
            int dj = (ib + ii) - jb;
            if (dj >= 0 && dj < 4) resf[dj] = 0.0f;
        }
    }

    // ---- Direct stores: rows i0+ib.., cols j0+jb.. ----
    const int gjbase = j0 + jb;
#pragma unroll
    for (int ii = 0; ii < 4; ii++) {
        const int gi = i0 + ib + ii;
        if (gi < nb && gjbase + 3 < nb) {
            *reinterpret_cast<float4*>(&out[(size_t)gi * nb + gjbase]) = res[ii];
        } else if (gi < nb) {
            const float* resf = &res[ii].x;
#pragma unroll
            for (int jj = 0; jj < 4; jj++)
                if (gjbase + jj < nb) out[(size_t)gi * nb + gjbase + jj] = resf[jj];
        }
    }

    // ---- Mirror stores (g is symmetric): rows j0+jb.., cols i0+ib.. ----
    if (!diagblk) {
        const int gibase = i0 + ib;
        const float* r0 = &res[0].x;
        const float* r1 = &res[1].x;
        const float* r2 = &res[2].x;
        const float* r3 = &res[3].x;
#pragma unroll
        for (int jj = 0; jj < 4; jj++) {
            const int gj = j0 + jb + jj;
            float4 v = make_float4(r0[jj], r1[jj], r2[jj], r3[jj]);
            if (gj < nb && gibase + 3 < nb) {
                *reinterpret_cast<float4*>(&out[(size_t)gj * nb + gibase]) = v;
            } else if (gj < nb) {
                const float* vf = &v.x;
#pragma unroll
                for (int ii = 0; ii < 4; ii++)
                    if (gibase + ii < nb) out[(size_t)gj * nb + gibase + ii] = vf[ii];
            }
        }
    }
}

extern "C" void kernel_launch(void* const* d_in, const int* in_sizes, int n_in,
                              void* d_out, int out_size) {
    const float* boxes = (const float*)d_in[0];
    float* out = (float*)d_out;
    const int nb = in_sizes[0] / 5;

    prep_kernel<<<(nb + 255) / 256, 256>>>(boxes, nb);

    const int T = (nb + TILE - 1) / TILE;
    const int nblk = T * (T + 1) / 2;
    pair_kernel<<<nblk, 256>>>(out, nb, T);
}

// round 10
// speedup vs baseline: 1.5829x; 1.0714x over previous
#include <cuda_runtime.h>

// Per-box preprocessed params: cx, cy, cos, sin, hx, hy, pad, pad  (8 floats)
#define MAXB 8192
__device__ float g_params[MAXB * 8];

__global__ void prep_kernel(const float* __restrict__ boxes, int nb) {
    int i = blockIdx.x * blockDim.x + threadIdx.x;
    if (i >= nb) return;
    float cx = boxes[i * 5 + 0];
    float cy = boxes[i * 5 + 1];
    float hx = boxes[i * 5 + 2] * 0.5f;
    float hy = boxes[i * 5 + 3] * 0.5f;
    float ang = boxes[i * 5 + 4];
    float s, c;
    sincosf(ang, &s, &c);
    float4* p = reinterpret_cast<float4*>(&g_params[i * 8]);
    p[0] = make_float4(cx, cy, c, s);
    p[1] = make_float4(hx, hy, 0.0f, 0.0f);
}

// 1-D GIoU of [-r1, r1] vs [d-r2, d+r2], d = |q| — fully closed form:
//   a = r1+r2;  t = max(|r1-r2|, |q|);  g = (a-t)/(a+t)
__device__ __forceinline__ float giou_axis(float r1, float r2, float q) {
    float a = r1 + r2;
    float t = fmaxf(fabsf(r1 - r2), fabsf(q));
    return __fdividef(a - t, a + t);
}

#define TILE 64
#define TRS  68   // transposed-tile row stride in floats (64 + 4 pad)

__global__ __launch_bounds__(256) void pair_kernel(float* __restrict__ out, int nb, int T) {
    // Map linear block index -> upper-triangular tile pair (r <= c)
    const int b = blockIdx.x;
    float Tf = (float)T;
    int r = (int)floorf(((2.0f * Tf + 1.0f) -
                sqrtf((2.0f * Tf + 1.0f) * (2.0f * Tf + 1.0f) - 8.0f * (float)b)) * 0.5f);
    if (r < 0) r = 0;
    if (r > T - 1) r = T - 1;
    while (r > 0 && r * T - (r * (r - 1)) / 2 > b) --r;
    while ((r + 1) * T - ((r + 1) * r) / 2 <= b) ++r;
    const int c = r + (b - (r * T - (r * (r - 1)) / 2));

    const int i0 = r * TILE;
    const int j0 = c * TILE;
    const int tid = threadIdx.x;

    // SoA shared layout: [0,64) = i-tile, [64,128) = j-tile (16B aligned)
    __shared__ __align__(16) float s_cx[128];
    __shared__ __align__(16) float s_cy[128];
    __shared__ __align__(16) float s_c [128];
    __shared__ __align__(16) float s_s [128];
    __shared__ __align__(16) float s_hx[128];
    __shared__ __align__(16) float s_hy[128];
    // Transposed result tile (row j, col i), stride 68, XOR-swizzled columns
    __shared__ __align__(16) float s_tr[TILE * TRS];

    {
        int which = tid >> 7;          // 0 -> i tile, 1 -> j tile
        int slot  = (tid >> 1) & 63;
        int half  = tid & 1;
        int gidx  = (which ? j0 : i0) + slot;
        float4 v = half ? make_float4(1.0f, 1.0f, 0.0f, 0.0f)
                        : make_float4(0.0f, 0.0f, 1.0f, 0.0f);
        if (gidx < nb)
            v = reinterpret_cast<const float4*>(g_params)[gidx * 2 + half];
        int d = which * 64 + slot;
        if (half == 0) {
            s_cx[d] = v.x; s_cy[d] = v.y; s_c[d] = v.z; s_s[d] = v.w;
        } else {
            s_hx[d] = v.x; s_hy[d] = v.y;
        }
    }
    __syncthreads();

    const int tx = tid & 15;   // j sub-tile (4 boxes)
    const int ty = tid >> 4;   // i sub-tile (4 boxes)
    const int ib = ty * 4;
    const int jb = tx * 4;

    // Hoist the 4 j-box params via LDS.128 from SoA
    float4 CXJ = *reinterpret_cast<const float4*>(&s_cx[64 + jb]);
    float4 CYJ = *reinterpret_cast<const float4*>(&s_cy[64 + jb]);
    float4 CJ4 = *reinterpret_cast<const float4*>(&s_c [64 + jb]);
    float4 SJ4 = *reinterpret_cast<const float4*>(&s_s [64 + jb]);
    float4 HXJ = *reinterpret_cast<const float4*>(&s_hx[64 + jb]);
    float4 HYJ = *reinterpret_cast<const float4*>(&s_hy[64 + jb]);
    const float* cxj = &CXJ.x;
    const float* cyj = &CYJ.x;
    const float* cj  = &CJ4.x;
    const float* sj  = &SJ4.x;
    const float* hxj = &HXJ.x;
    const float* hyj = &HYJ.x;

    const bool diagblk = (i0 == j0);

    float4 res[4];   // res[ii] = row of 4 results

#pragma unroll
    for (int ii = 0; ii < 4; ii++) {
        const float cxi = s_cx[ib + ii];
        const float cyi = s_cy[ib + ii];
        const float ci  = s_c [ib + ii];
        const float si  = s_s [ib + ii];
        const float hxi = s_hx[ib + ii];
        const float hyi = s_hy[ib + ii];

        float* resf = &res[ii].x;
#pragma unroll
        for (int jj = 0; jj < 4; jj++) {
            const float dx = cxj[jj] - cxi;
            const float dy = cyj[jj] - cyi;
            const float cd = fmaf(ci, cj[jj], si * sj[jj]);
            const float sd = fmaf(si, cj[jj], -(ci * sj[jj]));
            const float A  = fabsf(cd);
            const float Bb = fabsf(sd);
            const float q1 = fmaf(dx, ci, -(dy * si));
            const float q2 = fmaf(dx, si, dy * ci);
            const float q3 = fmaf(dx, cj[jj], -(dy * sj[jj]));
            const float q4 = fmaf(dx, sj[jj], dy * cj[jj]);
            const float r21 = fmaf(hxj[jj], A,  hyj[jj] * Bb);
            const float r22 = fmaf(hxj[jj], Bb, hyj[jj] * A);
            const float r23 = fmaf(hxi,     A,  hyi * Bb);
            const float r24 = fmaf(hxi,     Bb, hyi * A);

            float g1 = giou_axis(hxi,     r21, q1);
            float g2 = giou_axis(hyi,     r22, q2);
            float g3 = giou_axis(hxj[jj], r23, q3);
            float g4 = giou_axis(hyj[jj], r24, q4);

            float g = fminf(fminf(g1, g2), fminf(g3, g4));
            resf[jj] = fmaxf(g, 0.0f);
        }

        if (diagblk) {
            int dj = (ib + ii) - jb;
            if (dj >= 0 && dj < 4) resf[dj] = 0.0f;
        }
    }

    // ---- Stage transposed tile into smem (register 4x4 transpose + STS.128) ----
    // Row j = 4*tx + jj holds element columns i; XOR swizzle keeps banks clean.
    {
        const float* r0 = &res[0].x;
        const float* r1 = &res[1].x;
        const float* r2 = &res[2].x;
        const float* r3 = &res[3].x;
        const int colbase = (4 * ty) ^ ((tx & 7) << 2);
#pragma unroll
        for (int jj = 0; jj < 4; jj++) {
            float4 v = make_float4(r0[jj], r1[jj], r2[jj], r3[jj]);
            *reinterpret_cast<float4*>(&s_tr[(4 * tx + jj) * TRS + colbase]) = v;
        }
    }

    // ---- Direct stores: rows i0+ib.., cols j0+jb.. (coalesced) ----
    const int gjbase = j0 + jb;
#pragma unroll
    for (int ii = 0; ii < 4; ii++) {
        const int gi = i0 + ib + ii;
        if (gi < nb && gjbase + 3 < nb) {
            *reinterpret_cast<float4*>(&out[(size_t)gi * nb + gjbase]) = res[ii];
        } else if (gi < nb) {
            const float* resf = &res[ii].x;
#pragma unroll
            for (int jj = 0; jj < 4; jj++)
                if (gjbase + jj < nb) out[(size_t)gi * nb + gjbase + jj] = resf[jj];
        }
    }

    __syncthreads();

    // ---- Mirror stores from smem (coalesced rows of the transposed tile) ----
    if (!diagblk) {
        const int g4 = tid & 15;           // 16 float4 groups per row
        const int rbase = tid >> 4;        // 16 rows per pass
#pragma unroll
        for (int k = 0; k < 4; k++) {
            const int rho = rbase + 16 * k;            // row within j-tile
            const int colbase = (4 * g4) ^ (((rho >> 2) & 7) << 2);
            float4 v = *reinterpret_cast<const float4*>(&s_tr[rho * TRS + colbase]);
            const int gj = j0 + rho;
            const int gib = i0 + 4 * g4;
            if (gj < nb && gib + 3 < nb) {
                *reinterpret_cast<float4*>(&out[(size_t)gj * nb + gib]) = v;
            } else if (gj < nb) {
                const float* vf = &v.x;
#pragma unroll
                for (int ii = 0; ii < 4; ii++)
                    if (gib + ii < nb) out[(size_t)gj * nb + gib + ii] = vf[ii];
            }
        }
    }
}

extern "C" void kernel_launch(void* const* d_in, const int* in_sizes, int n_in,
                              void* d_out, int out_size) {
    const float* boxes = (const float*)d_in[0];
    float* out = (float*)d_out;
    const int nb = in_sizes[0] / 5;

    prep_kernel<<<(nb + 255) / 256, 256>>>(boxes, nb);

    const int T = (nb + TILE - 1) / TILE;
    const int nblk = T * (T + 1) / 2;
    pair_kernel<<<nblk, 256>>>(out, nb, T);
}